// round 1
// baseline (speedup 1.0000x reference)
#include <cuda_runtime.h>

// Problem dims (fixed by the reference)
#define C_DIM 2048
#define B_DIM 64
#define I_DIM 8
#define U_DIM 32
#define D_DIM 16
#define UD    512            // U*D
#define NBLK  148            // pass grid = #SMs
#define NTH   512            // pass threads

// ---- scratch (static __device__: allocation-free) ----
__device__ float g_xt[C_DIM * B_DIM * I_DIM];     // x transposed: [c][b][i]  (4 MB)
__device__ float g_spart[NBLK * B_DIM * UD];      // per-block s partials     (19 MB)
__device__ float g_v[B_DIM * UD];                 // squashed v               (128 KB)
__device__ float g_b[C_DIM * U_DIM];              // routing logits b_ij      (256 KB)

// x (B,I,C) -> g_xt[c][b][i]
__global__ void k_transpose(const float* __restrict__ x) {
    int idx = blockIdx.x * blockDim.x + threadIdx.x;
    if (idx >= C_DIM * B_DIM * I_DIM) return;
    int c = idx >> 9;
    int r = idx & 511;
    int b = r >> 3;
    int i = r & 7;
    g_xt[idx] = x[(b * I_DIM + i) * C_DIM + c];
}

// Fused routing pass.
// PASS==0: cij uniform (1/32), accumulate s1 partials.
// PASS==1: delta from v1, b = delta, cij = softmax(b), accumulate s2 partials.
// PASS==2: delta from v2, b += delta, cij = softmax(b), accumulate s3 partials.
template <int PASS>
__global__ void __launch_bounds__(NTH, 1) k_pass(const float* __restrict__ W) {
    extern __shared__ float u_sm[];      // [64][NTH] thread-private u_hat stash (PASS>0)
    __shared__ float red_sm[16][4];
    __shared__ float cij_sm[U_DIM];

    const int tid  = threadIdx.x;
    const int q    = tid >> 6;           // 0..7 : ud block of 64
    const int b    = tid & 63;           // batch index
    const int w    = tid >> 5;
    const int lane = tid & 31;

    float sacc[64];
#pragma unroll
    for (int j = 0; j < 64; j++) sacc[j] = 0.f;

    const int cbeg = (blockIdx.x * C_DIM) / NBLK;
    const int cend = ((blockIdx.x + 1) * C_DIM) / NBLK;

    for (int c = cbeg; c < cend; c++) {
        // x[b][0..7] for this c (coalesced: 32 lanes read 1 KB contiguous)
        const float4* xp = (const float4*)(g_xt + c * (B_DIM * I_DIM) + b * I_DIM);
        float4 x0 = xp[0], x1 = xp[1];
        float xb0 = x0.x, xb1 = x0.y, xb2 = x0.z, xb3 = x0.w;
        float xb4 = x1.x, xb5 = x1.y, xb6 = x1.z, xb7 = x1.w;

        const float* Wc = W + (size_t)c * (UD * I_DIM) + q * 64 * I_DIM;
        const float* vp = (PASS > 0) ? (g_v + b * UD + q * 64) : (const float*)0;

        float dpart[4] = {0.f, 0.f, 0.f, 0.f};

#pragma unroll
        for (int jj = 0; jj < 64; jj++) {
            // all lanes in a warp read the same W row -> uniform LDG, L1-hot
            const float4* wp = (const float4*)(Wc + jj * I_DIM);
            float4 w0 = __ldg(wp);
            float4 w1 = __ldg(wp + 1);
            float acc;
            acc = w0.x * xb0;
            acc = fmaf(w0.y, xb1, acc);
            acc = fmaf(w0.z, xb2, acc);
            acc = fmaf(w0.w, xb3, acc);
            acc = fmaf(w1.x, xb4, acc);
            acc = fmaf(w1.y, xb5, acc);
            acc = fmaf(w1.z, xb6, acc);
            acc = fmaf(w1.w, xb7, acc);
            if (PASS > 0) {
                dpart[jj >> 4] = fmaf(acc, __ldg(vp + jj), dpart[jj >> 4]);
                u_sm[jj * NTH + tid] = acc;          // private stash (no conflicts)
            } else {
                sacc[jj] += acc;
            }
        }

        if (PASS > 0) {
            // block reduction of delta over b (lanes) then warp pairs
#pragma unroll
            for (int k = 0; k < 4; k++) {
#pragma unroll
                for (int off = 16; off; off >>= 1)
                    dpart[k] += __shfl_down_sync(0xffffffffu, dpart[k], off);
            }
            if (lane == 0) {
                red_sm[w][0] = dpart[0];
                red_sm[w][1] = dpart[1];
                red_sm[w][2] = dpart[2];
                red_sm[w][3] = dpart[3];
            }
            __syncthreads();
            if (tid < U_DIM) {
                int u = tid;
                int qq = u >> 2, k = u & 3;
                float delta = (red_sm[2 * qq][k] + red_sm[2 * qq + 1][k]) * (1.0f / 64.0f);
                float bv = delta;
                if (PASS == 2) bv += g_b[c * U_DIM + u];
                g_b[c * U_DIM + u] = bv;
                // softmax over the 32 u's (one full warp)
                float m = bv;
#pragma unroll
                for (int off = 16; off; off >>= 1)
                    m = fmaxf(m, __shfl_xor_sync(0xffffffffu, m, off));
                float e = __expf(bv - m);
                float ssum = e;
#pragma unroll
                for (int off = 16; off; off >>= 1)
                    ssum += __shfl_xor_sync(0xffffffffu, ssum, off);
                cij_sm[u] = e / ssum;
            }
            __syncthreads();
#pragma unroll
            for (int jj = 0; jj < 64; jj++) {
                float cij = cij_sm[q * 4 + (jj >> 4)];
                sacc[jj] = fmaf(cij, u_sm[jj * NTH + tid], sacc[jj]);
            }
            // no trailing barrier needed: next write to red_sm happens after
            // the next __syncthreads; cij_sm writes are behind the next sync too
        }
    }

    const float scale = (PASS == 0) ? (1.0f / 32.0f) : 1.0f;
    float* sp = g_spart + (size_t)blockIdx.x * (B_DIM * UD) + b * UD + q * 64;
#pragma unroll
    for (int jj = 0; jj < 64; jj += 4) {
        float4 o = make_float4(sacc[jj] * scale, sacc[jj + 1] * scale,
                               sacc[jj + 2] * scale, sacc[jj + 3] * scale);
        *(float4*)(sp + jj) = o;
    }
}

// Reduce per-block s partials, apply squash (mag over U axis — reference quirk),
// write v (or final output).
__global__ void k_redsquash(float* __restrict__ dout, int final_out) {
    __shared__ float sq_sm[UD];
    __shared__ float r_sm[D_DIM];
    int b = blockIdx.x;
    int ud = threadIdx.x;      // 512 threads
    float val = 0.f;
    const float* sp = g_spart + b * UD + ud;
#pragma unroll 4
    for (int p = 0; p < NBLK; p++) val += sp[(size_t)p * (B_DIM * UD)];
    sq_sm[ud] = val * val;
    __syncthreads();
    if (ud < D_DIM) {
        float msq = 0.f;
#pragma unroll
        for (int u = 0; u < U_DIM; u++) msq += sq_sm[u * D_DIM + ud];
        r_sm[ud] = sqrtf(msq) / (1.0f + msq);   // mag_sq/((1+mag_sq)*mag)
    }
    __syncthreads();
    float v = val * r_sm[ud & 15];
    float* dst = final_out ? dout : g_v;
    dst[b * UD + ud] = v;
}

extern "C" void kernel_launch(void* const* d_in, const int* in_sizes, int n_in,
                              void* d_out, int out_size) {
    const float* x = (const float*)d_in[0];
    const float* W = (const float*)d_in[1];
    // robust against input ordering: x has 1,048,576 elems, W has 8,388,608
    if (n_in >= 2 && in_sizes[0] == C_DIM * U_DIM * D_DIM * I_DIM) {
        const float* t = x; x = W; W = t;
    }
    float* out = (float*)d_out;

    cudaFuncSetAttribute(k_pass<1>, cudaFuncAttributeMaxDynamicSharedMemorySize,
                         64 * NTH * (int)sizeof(float));
    cudaFuncSetAttribute(k_pass<2>, cudaFuncAttributeMaxDynamicSharedMemorySize,
                         64 * NTH * (int)sizeof(float));

    k_transpose<<<(C_DIM * B_DIM * I_DIM + 255) / 256, 256>>>(x);

    // iteration 1: uniform cij -> s1 -> v1
    k_pass<0><<<NBLK, NTH>>>(W);
    k_redsquash<<<B_DIM, UD>>>(out, 0);

    // iteration 2: delta(v1), b=delta, softmax -> s2 -> v2
    k_pass<1><<<NBLK, NTH, 64 * NTH * sizeof(float)>>>(W);
    k_redsquash<<<B_DIM, UD>>>(out, 0);

    // iteration 3: delta(v2), b+=delta, softmax -> s3 -> v3 (output)
    k_pass<2><<<NBLK, NTH, 64 * NTH * sizeof(float)>>>(W);
    k_redsquash<<<B_DIM, UD>>>(out, 1);
}

// round 2
// speedup vs baseline: 2.8506x; 2.8506x over previous
#include <cuda_runtime.h>

#define C_DIM 2048
#define B_DIM 64
#define I_DIM 8
#define U_DIM 32
#define D_DIM 16
#define UD    512
#define NBLK  148
#define NTH   512

typedef unsigned long long u64;

// ---- scratch (static __device__: allocation-free) ----
__device__ float g_xt[C_DIM * B_DIM * I_DIM];     // x transposed: [c][b][i]
__device__ float g_spart[NBLK * B_DIM * UD];      // per-block s partials
__device__ float g_v[B_DIM * UD];                 // squashed v
__device__ float g_b[C_DIM * U_DIM];              // routing logits

__device__ __forceinline__ u64 mul2(u64 a, u64 b) {
    u64 r; asm("mul.rn.f32x2 %0, %1, %2;" : "=l"(r) : "l"(a), "l"(b)); return r;
}
__device__ __forceinline__ u64 fma2(u64 a, u64 b, u64 c) {
    u64 r; asm("fma.rn.f32x2 %0, %1, %2, %3;" : "=l"(r) : "l"(a), "l"(b), "l"(c)); return r;
}
__device__ __forceinline__ float hadd2(u64 a) {
    float lo, hi; asm("mov.b64 {%0,%1}, %2;" : "=f"(lo), "=f"(hi) : "l"(a));
    return lo + hi;
}
// volatile load: stops the compiler hoisting 64 c-invariant v loads into regs (spill bomb)
__device__ __forceinline__ float ldg_v(const float* p) {
    float r; asm volatile("ld.global.nc.f32 %0, [%1];" : "=f"(r) : "l"(p)); return r;
}

// x (B,I,C) -> g_xt[c][b][i]
__global__ void k_transpose(const float* __restrict__ x) {
    int idx = blockIdx.x * blockDim.x + threadIdx.x;
    if (idx >= C_DIM * B_DIM * I_DIM) return;
    int c = idx >> 9;
    int r = idx & 511;
    int b = r >> 3;
    int i = r & 7;
    g_xt[idx] = x[(b * I_DIM + i) * C_DIM + c];
}

// Fused routing pass. Warp w owns batches b = 4w..4w+3 (r=0..3).
// Lane l owns ud = 32k + l for k=0..15  (u = 2k + (l>>4), d = l&15).
template <int PASS>
__global__ void __launch_bounds__(NTH, 1) k_pass(const float* __restrict__ W) {
    extern __shared__ float4 u_sm4[];          // [16][NTH] u_hat stash (PASS>0)
    __shared__ float red_sm[16][32];
    __shared__ float cij_sm[U_DIM];

    const int tid  = threadIdx.x;
    const int w    = tid >> 5;
    const int lane = tid & 31;
    const int hw   = lane >> 4;

    float sacc[16][4];
#pragma unroll
    for (int k = 0; k < 16; k++)
#pragma unroll
        for (int r = 0; r < 4; r++) sacc[k][r] = 0.f;

    const int cbeg = (blockIdx.x * C_DIM) / NBLK;
    const int cend = ((blockIdx.x + 1) * C_DIM) / NBLK;

    for (int c = cbeg; c < cend; c++) {
        // x for this warp's 4 batches, packed as f32x2 lanes (bit-identical reinterpret)
        u64 xp[4][4];
        const ulonglong2* xb = (const ulonglong2*)(g_xt + c * (B_DIM * I_DIM) + (w * 4) * I_DIM);
#pragma unroll
        for (int r = 0; r < 4; r++) {
            ulonglong2 a0 = xb[2 * r], a1 = xb[2 * r + 1];
            xp[r][0] = a0.x; xp[r][1] = a0.y; xp[r][2] = a1.x; xp[r][3] = a1.y;
        }
        const ulonglong2* Wp = (const ulonglong2*)(W + (size_t)c * (UD * I_DIM)) + lane * 2;
        const float* vbase = g_v + (w * 4) * UD + lane;

#pragma unroll
        for (int k = 0; k < 16; k++) {
            // W[c, ud=32k+lane, 0..7]: lane-coalesced 128-bit loads, reused for 4 b's
            ulonglong2 wA = Wp[k * 64];
            ulonglong2 wB = Wp[k * 64 + 1];
            float uu[4];
            float dp = 0.f;
#pragma unroll
            for (int r = 0; r < 4; r++) {
                u64 acc = mul2(wA.x, xp[r][0]);
                acc = fma2(wA.y, xp[r][1], acc);
                acc = fma2(wB.x, xp[r][2], acc);
                acc = fma2(wB.y, xp[r][3], acc);
                uu[r] = hadd2(acc);
                if (PASS > 0) {
                    float vv = ldg_v(vbase + r * UD + k * 32);   // coalesced, L1-hot
                    dp = fmaf(uu[r], vv, dp);
                } else {
                    sacc[k][r] += uu[r];
                }
            }
            if (PASS > 0) {
                u_sm4[k * NTH + tid] = make_float4(uu[0], uu[1], uu[2], uu[3]);
                // sum over d (16-lane segments)
#pragma unroll
                for (int off = 8; off; off >>= 1)
                    dp += __shfl_down_sync(0xffffffffu, dp, off, 16);
                if ((lane & 15) == 0) red_sm[w][2 * k + hw] = dp;
            }
        }

        if (PASS > 0) {
            __syncthreads();
            if (tid < U_DIM) {
                int u = tid;
                float delta = 0.f;
#pragma unroll
                for (int ww = 0; ww < 16; ww++) delta += red_sm[ww][u];
                float bv = delta * (1.0f / 64.0f);
                if (PASS == 2) bv += g_b[c * U_DIM + u];
                g_b[c * U_DIM + u] = bv;
                float m = bv;
#pragma unroll
                for (int off = 16; off; off >>= 1)
                    m = fmaxf(m, __shfl_xor_sync(0xffffffffu, m, off));
                float e = __expf(bv - m);
                float s = e;
#pragma unroll
                for (int off = 16; off; off >>= 1)
                    s += __shfl_xor_sync(0xffffffffu, s, off);
                cij_sm[u] = e / s;
            }
            __syncthreads();
#pragma unroll
            for (int k = 0; k < 16; k++) {
                float cij = cij_sm[2 * k + hw];
                float4 uq = u_sm4[k * NTH + tid];
                sacc[k][0] = fmaf(cij, uq.x, sacc[k][0]);
                sacc[k][1] = fmaf(cij, uq.y, sacc[k][1]);
                sacc[k][2] = fmaf(cij, uq.z, sacc[k][2]);
                sacc[k][3] = fmaf(cij, uq.w, sacc[k][3]);
            }
        }
    }

    const float scale = (PASS == 0) ? (1.0f / 32.0f) : 1.0f;
    float* spb = g_spart + (size_t)blockIdx.x * (B_DIM * UD);
#pragma unroll
    for (int r = 0; r < 4; r++) {
        float* sp = spb + (w * 4 + r) * UD + lane;
#pragma unroll
        for (int k = 0; k < 16; k++) sp[k * 32] = sacc[k][r] * scale;
    }
}

// Reduce per-block s partials, apply squash (mag over U axis — reference quirk).
__global__ void k_redsquash(float* __restrict__ dout, int final_out) {
    __shared__ float sq_sm[UD];
    __shared__ float r_sm[D_DIM];
    int b = blockIdx.x;
    int ud = threadIdx.x;      // 512 threads
    float val = 0.f;
    const float* sp = g_spart + b * UD + ud;
#pragma unroll 4
    for (int p = 0; p < NBLK; p++) val += sp[(size_t)p * (B_DIM * UD)];
    sq_sm[ud] = val * val;
    __syncthreads();
    if (ud < D_DIM) {
        float msq = 0.f;
#pragma unroll
        for (int u = 0; u < U_DIM; u++) msq += sq_sm[u * D_DIM + ud];
        r_sm[ud] = sqrtf(msq) / (1.0f + msq);   // mag_sq/((1+mag_sq)*mag)
    }
    __syncthreads();
    float v = val * r_sm[ud & 15];
    float* dst = final_out ? dout : g_v;
    dst[b * UD + ud] = v;
}

extern "C" void kernel_launch(void* const* d_in, const int* in_sizes, int n_in,
                              void* d_out, int out_size) {
    const float* x = (const float*)d_in[0];
    const float* W = (const float*)d_in[1];
    if (n_in >= 2 && in_sizes[0] == C_DIM * U_DIM * D_DIM * I_DIM) {
        const float* t = x; x = W; W = t;
    }
    float* out = (float*)d_out;

    const int STASH = 16 * NTH * (int)sizeof(float4);   // 128 KB
    cudaFuncSetAttribute(k_pass<1>, cudaFuncAttributeMaxDynamicSharedMemorySize, STASH);
    cudaFuncSetAttribute(k_pass<2>, cudaFuncAttributeMaxDynamicSharedMemorySize, STASH);

    k_transpose<<<(C_DIM * B_DIM * I_DIM + 255) / 256, 256>>>(x);

    // iteration 1: uniform cij -> s1 -> v1
    k_pass<0><<<NBLK, NTH>>>(W);
    k_redsquash<<<B_DIM, UD>>>(out, 0);

    // iteration 2: delta(v1), b=delta, softmax -> s2 -> v2
    k_pass<1><<<NBLK, NTH, STASH>>>(W);
    k_redsquash<<<B_DIM, UD>>>(out, 0);

    // iteration 3: delta(v2), b+=delta, softmax -> s3 -> v3 (output)
    k_pass<2><<<NBLK, NTH, STASH>>>(W);
    k_redsquash<<<B_DIM, UD>>>(out, 1);
}